// round 13
// baseline (speedup 1.0000x reference)
#include <cuda_runtime.h>
#include <cuda_bf16.h>
#include <cuda_fp16.h>
#include <cstdint>

#define NN 100000
#define NE 1600000
#define D  128
#define KK 256   // concat(x, neigh)

#define SCAN_NB ((NN + 255) / 256)   // 391

// ---- scratch (static device globals; no runtime allocation) ----
__device__ int   g_deg[NN];
__device__ float g_inv[NN];
__device__ int   g_rowptr[NN + 1];
__device__ int   g_cursor[NN];
__device__ int   g_esrc[NE];
__device__ int   g_part[SCAN_NB];
__device__ int   g_pscan[SCAN_NB];
__device__ __half g_hx[(size_t)NN * KK];   // fp16 A operand: cols 0-127 x, 128-255 neigh
__device__ __half g_Wh[3 * D * KK];        // W^T concat fp16, [layer][n][k]

// ================= helpers =================
__device__ __forceinline__ uint32_t smem_u32(const void* p) {
    uint32_t a;
    asm("{ .reg .u64 t; cvta.to.shared.u64 t, %1; cvt.u32.u64 %0, t; }"
        : "=r"(a) : "l"(p));
    return a;
}
#define LDSM4(d0, d1, d2, d3, addr)                                         \
    asm volatile("ldmatrix.sync.aligned.m8n8.x4.shared.b16 {%0,%1,%2,%3}, [%4];" \
                 : "=r"(d0), "=r"(d1), "=r"(d2), "=r"(d3) : "r"(addr))

__device__ __forceinline__ void mma_f16(float* c, const uint32_t* a,
                                        uint32_t b0, uint32_t b1) {
    asm volatile(
        "mma.sync.aligned.m16n8k16.row.col.f32.f16.f16.f32 "
        "{%0,%1,%2,%3}, {%4,%5,%6,%7}, {%8,%9}, {%0,%1,%2,%3};\n"
        : "+f"(c[0]), "+f"(c[1]), "+f"(c[2]), "+f"(c[3])
        : "r"(a[0]), "r"(a[1]), "r"(a[2]), "r"(a[3]), "r"(b0), "r"(b1));
}

#define CP_ASYNC(dst, src, sz)                                              \
    asm volatile("cp.async.cg.shared.global [%0], [%1], 16, %2;"            \
                 :: "r"(dst), "l"(src), "r"(sz))
#define CP_COMMIT() asm volatile("cp.async.commit_group;" ::: "memory")
#define CP_WAIT1()  asm volatile("cp.async.wait_group 1;" ::: "memory")
#define CP_WAIT0()  asm volatile("cp.async.wait_group 0;" ::: "memory")

#define GRIDDEP_WAIT()   asm volatile("griddepcontrol.wait;" ::: "memory")
#define GRIDDEP_LAUNCH() asm volatile("griddepcontrol.launch_dependents;" :::)

__device__ __forceinline__ uint32_t swz(int r, int c) {
    return (uint32_t)(r * 64 + ((c ^ ((r >> 1) & 3)) << 4));
}

// ================= one-time conversions =================
__global__ void k_cvtw(const float* __restrict__ Ws, const float* __restrict__ Wn) {
    int id = blockIdx.x * blockDim.x + threadIdx.x;
    if (id >= 3 * KK * D) return;
    int n = id & (D - 1);
    int k = (id >> 7) & (KK - 1);
    int l = id >> 15;
    float v = (k < D) ? Ws[(l * D + k) * D + n] : Wn[(l * D + (k - D)) * D + n];
    g_Wh[(l * D + n) * KK + k] = __float2half_rn(v);
}

__global__ void k_cvtx(const float4* __restrict__ x4) {
    int id = blockIdx.x * blockDim.x + threadIdx.x;
    if (id >= NN * 32) return;
    int row = id >> 5, j = id & 31;
    float4 v = x4[id];
    __half2* ph = (__half2*)(g_hx + (size_t)row * KK + j * 4);
    ph[0] = __floats2half2_rn(v.x, v.y);
    ph[1] = __floats2half2_rn(v.z, v.w);
}

// ================= CSR build =================
__global__ void k_count(const int4* __restrict__ dst4) {
    int e = blockIdx.x * blockDim.x + threadIdx.x;
    if (e < NE / 4) {
        int4 d = __ldg(dst4 + e);
        atomicAdd(&g_deg[d.x], 1);
        atomicAdd(&g_deg[d.y], 1);
        atomicAdd(&g_deg[d.z], 1);
        atomicAdd(&g_deg[d.w], 1);
    }
}

__global__ void k_part() {
    int i = blockIdx.x * 256 + threadIdx.x;
    int lane = threadIdx.x & 31, warp = threadIdx.x >> 5;
    int v = (i < NN) ? g_deg[i] : 0;
#pragma unroll
    for (int off = 16; off > 0; off >>= 1)
        v += __shfl_down_sync(0xFFFFFFFFu, v, off);
    __shared__ int ws[8];
    if (lane == 0) ws[warp] = v;
    __syncthreads();
    if (threadIdx.x < 8) {
        int s = ws[threadIdx.x];
#pragma unroll
        for (int off = 4; off > 0; off >>= 1)
            s += __shfl_down_sync(0xFFu, s, off);
        if (threadIdx.x == 0) g_part[blockIdx.x] = s;
    }
}

__global__ void k_scanp() {
    __shared__ int sp[512];
    int t = threadIdx.x;
    sp[t] = (t < SCAN_NB) ? g_part[t] : 0;
    __syncthreads();
#pragma unroll
    for (int off = 1; off < 512; off <<= 1) {
        int v = (t >= off) ? sp[t - off] : 0;
        __syncthreads();
        sp[t] += v;
        __syncthreads();
    }
    if (t < SCAN_NB) g_pscan[t] = (t == 0) ? 0 : sp[t - 1];
}

__global__ void k_write() {
    int i = blockIdx.x * 256 + threadIdx.x;
    int lane = threadIdx.x & 31, warp = threadIdx.x >> 5;
    int d = (i < NN) ? g_deg[i] : 0;
    int x = d;
#pragma unroll
    for (int off = 1; off < 32; off <<= 1) {
        int y = __shfl_up_sync(0xFFFFFFFFu, x, off);
        if (lane >= off) x += y;
    }
    __shared__ int ws[8];
    if (lane == 31) ws[warp] = x;
    __syncthreads();
    if (warp == 0 && lane < 8) {
        int s = ws[lane];
#pragma unroll
        for (int off = 1; off < 8; off <<= 1) {
            int y = __shfl_up_sync(0xFFu, s, off);
            if (lane >= off) s += y;
        }
        ws[lane] = s;
    }
    __syncthreads();
    int base = g_pscan[blockIdx.x] + ((warp == 0) ? 0 : ws[warp - 1]);
    int excl = base + x - d;
    if (i < NN) {
        g_rowptr[i] = excl;
        g_cursor[i] = excl;
        g_inv[i]    = 1.0f / (float)max(d, 1);
        if (i == NN - 1) g_rowptr[NN] = excl + d;
    }
}

__global__ void k_fill(const int4* __restrict__ src4, const int4* __restrict__ dst4) {
    GRIDDEP_LAUNCH();   // let agg launch early; it waits before touching esrc
    int e = blockIdx.x * blockDim.x + threadIdx.x;
    if (e < NE / 4) {
        int4 d = __ldg(dst4 + e);
        int4 s = __ldg(src4 + e);
        g_esrc[atomicAdd(&g_cursor[d.x], 1)] = s.x;
        g_esrc[atomicAdd(&g_cursor[d.y], 1)] = s.y;
        g_esrc[atomicAdd(&g_cursor[d.z], 1)] = s.z;
        g_esrc[atomicAdd(&g_cursor[d.w], 1)] = s.w;
    }
}

// ================= aggregation: fp16 gather, fp32 acc, fp16 neigh write ====
// PDL: signals its own dependent (GEMM) immediately; waits for its
// predecessor (fill, or previous-layer GEMM) before reading esrc / g_hx.
__global__ void k_agg() {
    GRIDDEP_LAUNCH();
    int w    = (blockIdx.x * blockDim.x + threadIdx.x) >> 5;
    int lane = threadIdx.x & 31;
    if (w >= NN) {
        GRIDDEP_WAIT();
        return;
    }
    int beg = g_rowptr[w];
    int end = g_rowptr[w + 1];
    float iv = g_inv[w];
    GRIDDEP_WAIT();     // esrc (layer 0) / g_hx x-cols (layers 1,2) now final
    float4 a0 = make_float4(0.f, 0.f, 0.f, 0.f);
    float4 a1 = make_float4(0.f, 0.f, 0.f, 0.f);
    float4 a2 = make_float4(0.f, 0.f, 0.f, 0.f);
    float4 a3 = make_float4(0.f, 0.f, 0.f, 0.f);
    const uint2* hx = (const uint2*)g_hx;   // row = 64 uint2 (256 halfs); x = first 32
    int e = beg;
    for (; e + 3 < end; e += 4) {
        int s0 = g_esrc[e], s1 = g_esrc[e + 1], s2 = g_esrc[e + 2], s3 = g_esrc[e + 3];
        uint2 u0 = __ldg(hx + (long)s0 * 64 + lane);
        uint2 u1 = __ldg(hx + (long)s1 * 64 + lane);
        uint2 u2 = __ldg(hx + (long)s2 * 64 + lane);
        uint2 u3 = __ldg(hx + (long)s3 * 64 + lane);
        float2 p, q;
        p = __half22float2(*(__half2*)&u0.x); q = __half22float2(*(__half2*)&u0.y);
        a0.x += p.x; a0.y += p.y; a0.z += q.x; a0.w += q.y;
        p = __half22float2(*(__half2*)&u1.x); q = __half22float2(*(__half2*)&u1.y);
        a1.x += p.x; a1.y += p.y; a1.z += q.x; a1.w += q.y;
        p = __half22float2(*(__half2*)&u2.x); q = __half22float2(*(__half2*)&u2.y);
        a2.x += p.x; a2.y += p.y; a2.z += q.x; a2.w += q.y;
        p = __half22float2(*(__half2*)&u3.x); q = __half22float2(*(__half2*)&u3.y);
        a3.x += p.x; a3.y += p.y; a3.z += q.x; a3.w += q.y;
    }
    for (; e < end; e++) {
        int s0 = g_esrc[e];
        uint2 u0 = __ldg(hx + (long)s0 * 64 + lane);
        float2 p = __half22float2(*(__half2*)&u0.x);
        float2 q = __half22float2(*(__half2*)&u0.y);
        a0.x += p.x; a0.y += p.y; a0.z += q.x; a0.w += q.y;
    }
    float rx = (a0.x + a1.x + a2.x + a3.x) * iv;
    float ry = (a0.y + a1.y + a2.y + a3.y) * iv;
    float rz = (a0.z + a1.z + a2.z + a3.z) * iv;
    float rw = (a0.w + a1.w + a2.w + a3.w) * iv;
    __half2* pn = (__half2*)(g_hx + (size_t)w * KK + D + lane * 4);
    pn[0] = __floats2half2_rn(rx, ry);
    pn[1] = __floats2half2_rn(rz, rw);
}

// ================= fp16 HMMA GEMM (single term), cp.async 3-stage =========
// PDL: chunks 0-3 (x half) are agg-independent; wait sits before issue(4).
// Signals launch_dependents after the mainloop so the next agg overlaps the
// epilogue.
#define STAGE_SZ 16384
#define T_WH 8192

extern __shared__ __align__(16) uint8_t dynsm[];

__global__ void __launch_bounds__(256, 2) k_gemm(
    float* __restrict__ out, const float* __restrict__ bias,
    int layer, int final_layer)
{
    const int t    = threadIdx.x;
    const int warp = t >> 5;
    const int lane = t & 31;
    const int warpRow = (warp >> 1) * 32;
    const int warpCol = (warp & 1) * 64;
    const long rowBase = (long)blockIdx.x * 128;

    const uint32_t sbase = smem_u32(dynsm);
    const int jq = lane >> 3;
    const int rr = lane & 7;

    const __half* gW_h = g_Wh + (size_t)layer * D * KK;

    const int r0s = (t + 0)   >> 2, c0s = (t + 0)   & 3;
    const int r1s = (t + 256) >> 2, c1s = (t + 256) & 3;

    float acc[2][8][4];
#pragma unroll
    for (int i = 0; i < 2; i++)
#pragma unroll
        for (int j = 0; j < 8; j++)
#pragma unroll
            for (int q = 0; q < 4; q++) acc[i][j][q] = 0.f;

    auto issue = [&](int kc, int stage) {
        const uint32_t base = sbase + stage * STAGE_SZ;
        const int koff = kc * 32;
#pragma unroll
        for (int i = 0; i < 2; i++) {
            const int r = i ? r1s : r0s;
            const int c = i ? c1s : c0s;
            long row = rowBase + r;
            uint32_t sz = (row < NN) ? 16u : 0u;
            long arow = (row < NN) ? row : 0;
            const void* pA  = g_hx + arow * KK + koff + c * 8;
            const void* pWh = gW_h + (size_t)r * KK + koff + c * 8;
            uint32_t o = swz(r, c);
            CP_ASYNC(base + o,        pA,  sz);
            CP_ASYNC(base + o + T_WH, pWh, 16u);
        }
        CP_COMMIT();
    };

    issue(0, 0);

    for (int kc = 0; kc < 8; kc++) {
        const int stage = kc % 3;
        if (kc == 3) GRIDDEP_WAIT();   // neigh cols (chunks 4-7) need agg done
        if (kc < 7) issue(kc + 1, (kc + 1) % 3);
        if (kc < 7) { CP_WAIT1(); } else { CP_WAIT0(); }
        __syncthreads();

        const uint32_t base = sbase + stage * STAGE_SZ;
#pragma unroll
        for (int ks = 0; ks < 2; ks++) {
            uint32_t af[2][4];
#pragma unroll
            for (int ma = 0; ma < 2; ma++) {
                int ra = warpRow + ma * 16 + (jq & 1) * 8 + rr;
                int ca = ks * 2 + (jq >> 1);
                LDSM4(af[ma][0], af[ma][1], af[ma][2], af[ma][3], base + swz(ra, ca));
            }
#pragma unroll
            for (int g = 0; g < 4; g++) {
                int rb = warpCol + g * 16 + (jq >> 1) * 8 + rr;
                int cb = ks * 2 + (jq & 1);
                uint32_t bh[4];
                LDSM4(bh[0], bh[1], bh[2], bh[3], base + swz(rb, cb) + T_WH);
#pragma unroll
                for (int sub = 0; sub < 2; sub++) {
                    int na = g * 2 + sub;
                    uint32_t b0h = bh[sub * 2], b1h = bh[sub * 2 + 1];
#pragma unroll
                    for (int ma = 0; ma < 2; ma++) {
                        mma_f16(acc[ma][na], af[ma], b0h, b1h);
                    }
                }
            }
        }
        __syncthreads();
    }

    GRIDDEP_LAUNCH();   // next layer's agg can launch during the epilogue

    const float* bl = bias + (size_t)layer * D;
    const int q2 = (lane & 3) * 2;
    const int rq = lane >> 2;
#pragma unroll
    for (int na = 0; na < 8; na++) {
        int col = warpCol + na * 8 + q2;
        float2 bv = *(const float2*)(bl + col);
#pragma unroll
        for (int ma = 0; ma < 2; ma++) {
            float* c = acc[ma][na];
            long r0 = rowBase + warpRow + ma * 16 + rq;
#pragma unroll
            for (int h = 0; h < 2; h++) {
                long row = r0 + h * 8;
                if (row >= NN) continue;
                float ox = c[h * 2 + 0] + bv.x;
                float oy = c[h * 2 + 1] + bv.y;
                if (final_layer) {
                    *(float2*)(out + row * D + col) = make_float2(ox, oy);
                } else {
                    ox = fmaxf(ox, 0.f);
                    oy = fmaxf(oy, 0.f);
                    *(__half2*)(g_hx + (size_t)row * KK + col) =
                        __floats2half2_rn(ox, oy);
                }
            }
        }
    }
}

// ---------------------------------------------------------------
extern "C" void kernel_launch(void* const* d_in, const int* in_sizes, int n_in,
                              void* d_out, int out_size) {
    const float* emb = (const float*)d_in[0];
    const float* Ws  = (const float*)d_in[1];
    const float* Wn  = (const float*)d_in[2];
    const float* b   = (const float*)d_in[3];
    const int*   src = (const int*)d_in[4];
    const int*   dst = (const int*)d_in[5];
    float*       out = (float*)d_out;

    void* pdeg;
    cudaGetSymbolAddress(&pdeg, g_deg);

    cudaFuncSetAttribute(k_gemm, cudaFuncAttributeMaxDynamicSharedMemorySize,
                         3 * STAGE_SZ);

    static cudaStream_t s1 = nullptr;
    static cudaEvent_t evFork = nullptr, evJoin = nullptr;
    if (s1 == nullptr) {
        cudaStreamCreateWithFlags(&s1, cudaStreamNonBlocking);
        cudaEventCreateWithFlags(&evFork, cudaEventDisableTiming);
        cudaEventCreateWithFlags(&evJoin, cudaEventDisableTiming);
    }

    // fork: conversions on s1, CSR build on main stream
    cudaEventRecord(evFork, 0);
    cudaStreamWaitEvent(s1, evFork, 0);
    k_cvtw<<<(3 * KK * D + 255) / 256, 256, 0, s1>>>(Ws, Wn);
    k_cvtx<<<(NN * 32 + 255) / 256, 256, 0, s1>>>((const float4*)emb);
    cudaEventRecord(evJoin, s1);

    cudaMemsetAsync(pdeg, 0, NN * sizeof(int));
    k_count<<<(NE / 4 + 255) / 256, 256>>>((const int4*)dst);
    k_part<<<SCAN_NB, 256>>>();
    k_scanp<<<1, 512>>>();
    k_write<<<SCAN_NB, 256>>>();
    k_fill<<<(NE / 4 + 255) / 256, 256>>>((const int4*)src, (const int4*)dst);

    cudaStreamWaitEvent(0, evJoin, 0);

    const int aggGrid  = (NN + 7) / 8;
    const int gemmGrid = (NN + 127) / 128;

    cudaLaunchAttribute attrs[1];
    attrs[0].id = cudaLaunchAttributeProgrammaticStreamSerialization;
    attrs[0].val.programmaticStreamSerializationAllowed = 1;

    cudaLaunchConfig_t cfgAgg = {};
    cfgAgg.gridDim  = {(unsigned)aggGrid, 1, 1};
    cfgAgg.blockDim = {256, 1, 1};
    cfgAgg.dynamicSmemBytes = 0;
    cfgAgg.stream = 0;
    cfgAgg.attrs = attrs;
    cfgAgg.numAttrs = 1;

    cudaLaunchConfig_t cfgGemm = {};
    cfgGemm.gridDim  = {(unsigned)gemmGrid, 1, 1};
    cfgGemm.blockDim = {256, 1, 1};
    cfgGemm.dynamicSmemBytes = 3 * STAGE_SZ;
    cfgGemm.stream = 0;
    cfgGemm.attrs = attrs;
    cfgGemm.numAttrs = 1;

    cudaLaunchKernelEx(&cfgAgg, k_agg);
    cudaLaunchKernelEx(&cfgGemm, k_gemm, out, (const float*)b, 0, 0);

    cudaLaunchKernelEx(&cfgAgg, k_agg);
    cudaLaunchKernelEx(&cfgGemm, k_gemm, out, (const float*)b, 1, 0);

    cudaLaunchKernelEx(&cfgAgg, k_agg);
    cudaLaunchKernelEx(&cfgGemm, k_gemm, out, (const float*)b, 2, 1);
}

// round 14
// speedup vs baseline: 1.0587x; 1.0587x over previous
#include <cuda_runtime.h>
#include <cuda_bf16.h>
#include <cuda_fp16.h>
#include <cstdint>

#define NN 100000
#define NE 1600000
#define D  128
#define KK 256   // concat(x, neigh)

#define SCAN_NB ((NN + 255) / 256)   // 391

// ---- scratch (static device globals; no runtime allocation) ----
__device__ int   g_deg[NN];
__device__ float g_inv[NN];
__device__ int   g_rowptr[NN + 1];
__device__ int   g_cursor[NN];
__device__ int   g_esrc[NE];
__device__ int   g_part[SCAN_NB];
__device__ int   g_pscan[SCAN_NB];
__device__ __half g_hx[(size_t)NN * KK];   // fp16 A operand: cols 0-127 x, 128-255 neigh
__device__ __half g_Wh[3 * D * KK];        // W^T concat fp16, [layer][n][k]

// ================= helpers =================
__device__ __forceinline__ uint32_t smem_u32(const void* p) {
    uint32_t a;
    asm("{ .reg .u64 t; cvta.to.shared.u64 t, %1; cvt.u32.u64 %0, t; }"
        : "=r"(a) : "l"(p));
    return a;
}
#define LDSM4(d0, d1, d2, d3, addr)                                         \
    asm volatile("ldmatrix.sync.aligned.m8n8.x4.shared.b16 {%0,%1,%2,%3}, [%4];" \
                 : "=r"(d0), "=r"(d1), "=r"(d2), "=r"(d3) : "r"(addr))

__device__ __forceinline__ void mma_f16(float* c, const uint32_t* a,
                                        uint32_t b0, uint32_t b1) {
    asm volatile(
        "mma.sync.aligned.m16n8k16.row.col.f32.f16.f16.f32 "
        "{%0,%1,%2,%3}, {%4,%5,%6,%7}, {%8,%9}, {%0,%1,%2,%3};\n"
        : "+f"(c[0]), "+f"(c[1]), "+f"(c[2]), "+f"(c[3])
        : "r"(a[0]), "r"(a[1]), "r"(a[2]), "r"(a[3]), "r"(b0), "r"(b1));
}

#define CP_ASYNC(dst, src, sz)                                              \
    asm volatile("cp.async.cg.shared.global [%0], [%1], 16, %2;"            \
                 :: "r"(dst), "l"(src), "r"(sz))
#define CP_COMMIT() asm volatile("cp.async.commit_group;" ::: "memory")
#define CP_WAIT1()  asm volatile("cp.async.wait_group 1;" ::: "memory")
#define CP_WAIT0()  asm volatile("cp.async.wait_group 0;" ::: "memory")

#define GRIDDEP_WAIT()   asm volatile("griddepcontrol.wait;" ::: "memory")
#define GRIDDEP_LAUNCH() asm volatile("griddepcontrol.launch_dependents;" :::)

__device__ __forceinline__ uint32_t swz(int r, int c) {
    return (uint32_t)(r * 64 + ((c ^ ((r >> 1) & 3)) << 4));
}

// ================= one-time conversions =================
__global__ void k_cvtw(const float* __restrict__ Ws, const float* __restrict__ Wn) {
    int id = blockIdx.x * blockDim.x + threadIdx.x;
    if (id >= 3 * KK * D) return;
    int n = id & (D - 1);
    int k = (id >> 7) & (KK - 1);
    int l = id >> 15;
    float v = (k < D) ? Ws[(l * D + k) * D + n] : Wn[(l * D + (k - D)) * D + n];
    g_Wh[(l * D + n) * KK + k] = __float2half_rn(v);
}

__global__ void k_cvtx(const float4* __restrict__ x4) {
    int id = blockIdx.x * blockDim.x + threadIdx.x;
    if (id >= NN * 32) return;
    int row = id >> 5, j = id & 31;
    float4 v = x4[id];
    __half2* ph = (__half2*)(g_hx + (size_t)row * KK + j * 4);
    ph[0] = __floats2half2_rn(v.x, v.y);
    ph[1] = __floats2half2_rn(v.z, v.w);
}

// ================= CSR build =================
__global__ void k_count(const int4* __restrict__ dst4) {
    int e = blockIdx.x * blockDim.x + threadIdx.x;
    if (e < NE / 4) {
        int4 d = __ldg(dst4 + e);
        atomicAdd(&g_deg[d.x], 1);
        atomicAdd(&g_deg[d.y], 1);
        atomicAdd(&g_deg[d.z], 1);
        atomicAdd(&g_deg[d.w], 1);
    }
}

__global__ void k_part() {
    int i = blockIdx.x * 256 + threadIdx.x;
    int lane = threadIdx.x & 31, warp = threadIdx.x >> 5;
    int v = (i < NN) ? g_deg[i] : 0;
#pragma unroll
    for (int off = 16; off > 0; off >>= 1)
        v += __shfl_down_sync(0xFFFFFFFFu, v, off);
    __shared__ int ws[8];
    if (lane == 0) ws[warp] = v;
    __syncthreads();
    if (threadIdx.x < 8) {
        int s = ws[threadIdx.x];
#pragma unroll
        for (int off = 4; off > 0; off >>= 1)
            s += __shfl_down_sync(0xFFu, s, off);
        if (threadIdx.x == 0) g_part[blockIdx.x] = s;
    }
}

__global__ void k_scanp() {
    __shared__ int sp[512];
    int t = threadIdx.x;
    sp[t] = (t < SCAN_NB) ? g_part[t] : 0;
    __syncthreads();
#pragma unroll
    for (int off = 1; off < 512; off <<= 1) {
        int v = (t >= off) ? sp[t - off] : 0;
        __syncthreads();
        sp[t] += v;
        __syncthreads();
    }
    if (t < SCAN_NB) g_pscan[t] = (t == 0) ? 0 : sp[t - 1];
}

__global__ void k_write() {
    int i = blockIdx.x * 256 + threadIdx.x;
    int lane = threadIdx.x & 31, warp = threadIdx.x >> 5;
    int d = (i < NN) ? g_deg[i] : 0;
    int x = d;
#pragma unroll
    for (int off = 1; off < 32; off <<= 1) {
        int y = __shfl_up_sync(0xFFFFFFFFu, x, off);
        if (lane >= off) x += y;
    }
    __shared__ int ws[8];
    if (lane == 31) ws[warp] = x;
    __syncthreads();
    if (warp == 0 && lane < 8) {
        int s = ws[lane];
#pragma unroll
        for (int off = 1; off < 8; off <<= 1) {
            int y = __shfl_up_sync(0xFFu, s, off);
            if (lane >= off) s += y;
        }
        ws[lane] = s;
    }
    __syncthreads();
    int base = g_pscan[blockIdx.x] + ((warp == 0) ? 0 : ws[warp - 1]);
    int excl = base + x - d;
    if (i < NN) {
        g_rowptr[i] = excl;
        g_cursor[i] = excl;
        g_inv[i]    = 1.0f / (float)max(d, 1);
        if (i == NN - 1) g_rowptr[NN] = excl + d;
    }
}

__global__ void k_fill(const int4* __restrict__ src4, const int4* __restrict__ dst4) {
    int e = blockIdx.x * blockDim.x + threadIdx.x;
    if (e < NE / 4) {
        int4 d = __ldg(dst4 + e);
        int4 s = __ldg(src4 + e);
        g_esrc[atomicAdd(&g_cursor[d.x], 1)] = s.x;
        g_esrc[atomicAdd(&g_cursor[d.y], 1)] = s.y;
        g_esrc[atomicAdd(&g_cursor[d.z], 1)] = s.z;
        g_esrc[atomicAdd(&g_cursor[d.w], 1)] = s.w;
    }
}

// ================= aggregation: fp16 gather, fp32 acc, fp16 neigh write ====
__global__ void k_agg() {
    GRIDDEP_LAUNCH();   // allow dependent GEMM to begin its agg-independent half
    int w    = (blockIdx.x * blockDim.x + threadIdx.x) >> 5;
    int lane = threadIdx.x & 31;
    if (w >= NN) return;
    int beg = g_rowptr[w];
    int end = g_rowptr[w + 1];
    float4 a0 = make_float4(0.f, 0.f, 0.f, 0.f);
    float4 a1 = make_float4(0.f, 0.f, 0.f, 0.f);
    float4 a2 = make_float4(0.f, 0.f, 0.f, 0.f);
    float4 a3 = make_float4(0.f, 0.f, 0.f, 0.f);
    const uint2* hx = (const uint2*)g_hx;   // row = 64 uint2 (256 halfs); x = first 32
    int e = beg;
    for (; e + 3 < end; e += 4) {
        int s0 = g_esrc[e], s1 = g_esrc[e + 1], s2 = g_esrc[e + 2], s3 = g_esrc[e + 3];
        uint2 u0 = __ldg(hx + (long)s0 * 64 + lane);
        uint2 u1 = __ldg(hx + (long)s1 * 64 + lane);
        uint2 u2 = __ldg(hx + (long)s2 * 64 + lane);
        uint2 u3 = __ldg(hx + (long)s3 * 64 + lane);
        float2 p, q;
        p = __half22float2(*(__half2*)&u0.x); q = __half22float2(*(__half2*)&u0.y);
        a0.x += p.x; a0.y += p.y; a0.z += q.x; a0.w += q.y;
        p = __half22float2(*(__half2*)&u1.x); q = __half22float2(*(__half2*)&u1.y);
        a1.x += p.x; a1.y += p.y; a1.z += q.x; a1.w += q.y;
        p = __half22float2(*(__half2*)&u2.x); q = __half22float2(*(__half2*)&u2.y);
        a2.x += p.x; a2.y += p.y; a2.z += q.x; a2.w += q.y;
        p = __half22float2(*(__half2*)&u3.x); q = __half22float2(*(__half2*)&u3.y);
        a3.x += p.x; a3.y += p.y; a3.z += q.x; a3.w += q.y;
    }
    for (; e < end; e++) {
        int s0 = g_esrc[e];
        uint2 u0 = __ldg(hx + (long)s0 * 64 + lane);
        float2 p = __half22float2(*(__half2*)&u0.x);
        float2 q = __half22float2(*(__half2*)&u0.y);
        a0.x += p.x; a0.y += p.y; a0.z += q.x; a0.w += q.y;
    }
    float iv = g_inv[w];
    float rx = (a0.x + a1.x + a2.x + a3.x) * iv;
    float ry = (a0.y + a1.y + a2.y + a3.y) * iv;
    float rz = (a0.z + a1.z + a2.z + a3.z) * iv;
    float rw = (a0.w + a1.w + a2.w + a3.w) * iv;
    __half2* pn = (__half2*)(g_hx + (size_t)w * KK + D + lane * 4);
    pn[0] = __floats2half2_rn(rx, ry);
    pn[1] = __floats2half2_rn(rz, rw);
}

// ================= fp16 HMMA GEMM (single term), cp.async 3-stage =========
// block 128x128 out; 8 warps, warp 32x64; K=256 / 8 chunks of 32.
// stage = [A 8K | W 8K] = 16KB; acc += a*w.
// PDL: chunks 0-3 (x half) are agg-independent; griddepcontrol.wait is placed
// immediately before the first neigh-dependent cp.async (kc==3 -> issue(4)).
#define STAGE_SZ 16384
#define T_WH 8192

extern __shared__ __align__(16) uint8_t dynsm[];

__global__ void __launch_bounds__(256, 2) k_gemm(
    float* __restrict__ out, const float* __restrict__ bias,
    int layer, int final_layer)
{
    const int t    = threadIdx.x;
    const int warp = t >> 5;
    const int lane = t & 31;
    const int warpRow = (warp >> 1) * 32;
    const int warpCol = (warp & 1) * 64;
    const long rowBase = (long)blockIdx.x * 128;

    const uint32_t sbase = smem_u32(dynsm);
    const int jq = lane >> 3;
    const int rr = lane & 7;

    const __half* gW_h = g_Wh + (size_t)layer * D * KK;

    const int r0s = (t + 0)   >> 2, c0s = (t + 0)   & 3;
    const int r1s = (t + 256) >> 2, c1s = (t + 256) & 3;

    float acc[2][8][4];
#pragma unroll
    for (int i = 0; i < 2; i++)
#pragma unroll
        for (int j = 0; j < 8; j++)
#pragma unroll
            for (int q = 0; q < 4; q++) acc[i][j][q] = 0.f;

    auto issue = [&](int kc, int stage) {
        const uint32_t base = sbase + stage * STAGE_SZ;
        const int koff = kc * 32;
#pragma unroll
        for (int i = 0; i < 2; i++) {
            const int r = i ? r1s : r0s;
            const int c = i ? c1s : c0s;
            long row = rowBase + r;
            uint32_t sz = (row < NN) ? 16u : 0u;
            long arow = (row < NN) ? row : 0;
            const void* pA  = g_hx + arow * KK + koff + c * 8;
            const void* pWh = gW_h + (size_t)r * KK + koff + c * 8;
            uint32_t o = swz(r, c);
            CP_ASYNC(base + o,        pA,  sz);
            CP_ASYNC(base + o + T_WH, pWh, 16u);
        }
        CP_COMMIT();
    };

    issue(0, 0);

    for (int kc = 0; kc < 8; kc++) {
        const int stage = kc % 3;
        if (kc == 3) GRIDDEP_WAIT();   // neigh cols (chunks 4-7) need agg done
        if (kc < 7) issue(kc + 1, (kc + 1) % 3);
        if (kc < 7) { CP_WAIT1(); } else { CP_WAIT0(); }
        __syncthreads();

        const uint32_t base = sbase + stage * STAGE_SZ;
#pragma unroll
        for (int ks = 0; ks < 2; ks++) {
            uint32_t af[2][4];
#pragma unroll
            for (int ma = 0; ma < 2; ma++) {
                int ra = warpRow + ma * 16 + (jq & 1) * 8 + rr;
                int ca = ks * 2 + (jq >> 1);
                LDSM4(af[ma][0], af[ma][1], af[ma][2], af[ma][3], base + swz(ra, ca));
            }
#pragma unroll
            for (int g = 0; g < 4; g++) {
                int rb = warpCol + g * 16 + (jq >> 1) * 8 + rr;
                int cb = ks * 2 + (jq & 1);
                uint32_t bh[4];
                LDSM4(bh[0], bh[1], bh[2], bh[3], base + swz(rb, cb) + T_WH);
#pragma unroll
                for (int sub = 0; sub < 2; sub++) {
                    int na = g * 2 + sub;
                    uint32_t b0h = bh[sub * 2], b1h = bh[sub * 2 + 1];
#pragma unroll
                    for (int ma = 0; ma < 2; ma++) {
                        mma_f16(acc[ma][na], af[ma], b0h, b1h);
                    }
                }
            }
        }
        __syncthreads();
    }

    const float* bl = bias + (size_t)layer * D;
    const int q2 = (lane & 3) * 2;
    const int rq = lane >> 2;
#pragma unroll
    for (int na = 0; na < 8; na++) {
        int col = warpCol + na * 8 + q2;
        float2 bv = *(const float2*)(bl + col);
#pragma unroll
        for (int ma = 0; ma < 2; ma++) {
            float* c = acc[ma][na];
            long r0 = rowBase + warpRow + ma * 16 + rq;
#pragma unroll
            for (int h = 0; h < 2; h++) {
                long row = r0 + h * 8;
                if (row >= NN) continue;
                float ox = c[h * 2 + 0] + bv.x;
                float oy = c[h * 2 + 1] + bv.y;
                if (final_layer) {
                    *(float2*)(out + row * D + col) = make_float2(ox, oy);
                } else {
                    ox = fmaxf(ox, 0.f);
                    oy = fmaxf(oy, 0.f);
                    *(__half2*)(g_hx + (size_t)row * KK + col) =
                        __floats2half2_rn(ox, oy);
                }
            }
        }
    }
}

// ---------------------------------------------------------------
extern "C" void kernel_launch(void* const* d_in, const int* in_sizes, int n_in,
                              void* d_out, int out_size) {
    const float* emb = (const float*)d_in[0];
    const float* Ws  = (const float*)d_in[1];
    const float* Wn  = (const float*)d_in[2];
    const float* b   = (const float*)d_in[3];
    const int*   src = (const int*)d_in[4];
    const int*   dst = (const int*)d_in[5];
    float*       out = (float*)d_out;

    void* pdeg;
    cudaGetSymbolAddress(&pdeg, g_deg);

    cudaFuncSetAttribute(k_gemm, cudaFuncAttributeMaxDynamicSharedMemorySize,
                         3 * STAGE_SZ);

    static cudaStream_t s1 = nullptr;
    static cudaEvent_t evFork = nullptr, evJoin = nullptr;
    if (s1 == nullptr) {
        cudaStreamCreateWithFlags(&s1, cudaStreamNonBlocking);
        cudaEventCreateWithFlags(&evFork, cudaEventDisableTiming);
        cudaEventCreateWithFlags(&evJoin, cudaEventDisableTiming);
    }

    // fork: conversions on s1, CSR build on main stream
    cudaEventRecord(evFork, 0);
    cudaStreamWaitEvent(s1, evFork, 0);
    k_cvtw<<<(3 * KK * D + 255) / 256, 256, 0, s1>>>(Ws, Wn);
    k_cvtx<<<(NN * 32 + 255) / 256, 256, 0, s1>>>((const float4*)emb);
    cudaEventRecord(evJoin, s1);

    cudaMemsetAsync(pdeg, 0, NN * sizeof(int));
    k_count<<<(NE / 4 + 255) / 256, 256>>>((const int4*)dst);
    k_part<<<SCAN_NB, 256>>>();
    k_scanp<<<1, 512>>>();
    k_write<<<SCAN_NB, 256>>>();
    k_fill<<<(NE / 4 + 255) / 256, 256>>>((const int4*)src, (const int4*)dst);

    cudaStreamWaitEvent(0, evJoin, 0);

    const int aggGrid  = (NN + 7) / 8;
    const int gemmGrid = (NN + 127) / 128;

    // GEMM launches carry the PDL attribute so they can overlap agg's tail.
    cudaLaunchAttribute attrs[1];
    attrs[0].id = cudaLaunchAttributeProgrammaticStreamSerialization;
    attrs[0].val.programmaticStreamSerializationAllowed = 1;
    cudaLaunchConfig_t cfg = {};
    cfg.gridDim  = {(unsigned)gemmGrid, 1, 1};
    cfg.blockDim = {256, 1, 1};
    cfg.dynamicSmemBytes = 3 * STAGE_SZ;
    cfg.stream = 0;
    cfg.attrs = attrs;
    cfg.numAttrs = 1;

    k_agg<<<aggGrid, 256>>>();
    cudaLaunchKernelEx(&cfg, k_gemm, out, (const float*)b, 0, 0);

    k_agg<<<aggGrid, 256>>>();
    cudaLaunchKernelEx(&cfg, k_gemm, out, (const float*)b, 1, 0);

    k_agg<<<aggGrid, 256>>>();
    cudaLaunchKernelEx(&cfg, k_gemm, out, (const float*)b, 2, 1);
}